// round 14
// baseline (speedup 1.0000x reference)
#include <cuda_runtime.h>
#include <cstdint>
#include <math.h>

#define CH 512
#define NG 64
#define N_SAMP 16
#define H 64
#define W 64
#define HW 4096

#define SROWS 66
#define SCOLS 72                          // interior at col 4 -> 16B-aligned
#define CHT   (SROWS * SCOLS)             // 4752 floats
#define STILE (8 * CHT)                   // 38016 floats = 152064 B

// ===========================================================================
// ONE fused kernel. Grid (64, 16) x 512 threads, 1 CTA/SM (148KB smem).
//  0. style LDG early
//  1. content tile load (batched LDG.128), stats in regs; style -> st smem
//  2. prep: d via thread-per-(j, 8-channel chunk), 9 reg accumulators;
//     bias/S dots
//  3. finalize; conv (neighbor cols via warp shuffle) + collapse + norm
// ===========================================================================
__global__ void __launch_bounds__(512, 1) fused_kernel(
    const float* __restrict__ content,
    const float* __restrict__ style,
    const float* __restrict__ dw_w,
    const float* __restrict__ dw_b,
    const float* __restrict__ pk_w,
    const float* __restrict__ pk_b,
    const float* __restrict__ pb_w,
    const float* __restrict__ pb_b,
    float* __restrict__ out)
{
    extern __shared__ float s[];          // [8][SROWS][SCOLS] content tile
    __shared__ float st[16 * 512];        // style TRANSPOSED [pos][channel]
    __shared__ float sd[512];             // style spatial mean
    __shared__ float dredW[16 * 9];       // per-warp d partials
    __shared__ float fd[72];
    __shared__ float fb[8], fm[8], fr[8];
    __shared__ float red[32];
    __shared__ float fS_sh;

    int g = blockIdx.x;
    int n = blockIdx.y;
    int tid = threadIdx.x;
    int lane = tid & 31, warp = tid >> 5;
    int cbase = n * 512 + g * 8;

    // ============ 0. style LDG early =======================================
    const float4* sp = (const float4*)(style + (size_t)(n * 512 + tid) * 16);
    float4 a0 = sp[0], a1 = sp[1], a2 = sp[2], a3 = sp[3];

    // ============ 1. content tile load, stats in regs ======================
    int c    = warp >> 1;
    int half = warp & 1;
    float sum = 0.f, sq = 0.f;
    {
        const float* bc = content + (size_t)(cbase + c) * HW;
        float* sc = s + c * CHT;
        int sub = lane >> 4, q = lane & 15;

        #pragma unroll
        for (int b = 0; b < 4; b++) {
            int lr0 = half * 33 + (8 * b + sub);
            int lr1 = lr0 + 2, lr2 = lr0 + 4, lr3 = lr0 + 6;
            int gr0 = (lr0 == 0) ? 1 : (lr0 == 65 ? 62 : lr0 - 1);
            int gr1 = (lr1 == 0) ? 1 : (lr1 == 65 ? 62 : lr1 - 1);
            int gr2 = (lr2 == 0) ? 1 : (lr2 == 65 ? 62 : lr2 - 1);
            int gr3 = (lr3 == 0) ? 1 : (lr3 == 65 ? 62 : lr3 - 1);
            float4 v0 = *(const float4*)(bc + gr0 * W + 4 * q);
            float4 v1 = *(const float4*)(bc + gr1 * W + 4 * q);
            float4 v2 = *(const float4*)(bc + gr2 * W + 4 * q);
            float4 v3 = *(const float4*)(bc + gr3 * W + 4 * q);
            *(float4*)(sc + lr0 * SCOLS + 4 + 4 * q) = v0;
            *(float4*)(sc + lr1 * SCOLS + 4 + 4 * q) = v1;
            *(float4*)(sc + lr2 * SCOLS + 4 + 4 * q) = v2;
            *(float4*)(sc + lr3 * SCOLS + 4 + 4 * q) = v3;
            if (lr0 >= 1 && lr0 <= 64) {
                sum += v0.x + v0.y + v0.z + v0.w;
                sq  += v0.x * v0.x + v0.y * v0.y + v0.z * v0.z + v0.w * v0.w;
            }
            sum += v1.x + v1.y + v1.z + v1.w;       // lr1..lr3 always interior
            sq  += v1.x * v1.x + v1.y * v1.y + v1.z * v1.z + v1.w * v1.w;
            sum += v2.x + v2.y + v2.z + v2.w;
            sq  += v2.x * v2.x + v2.y * v2.y + v2.z * v2.z + v2.w * v2.w;
            sum += v3.x + v3.y + v3.z + v3.w;
            sq  += v3.x * v3.x + v3.y * v3.y + v3.z * v3.z + v3.w * v3.w;
        }
        if (sub == 0) {                              // tail row (rr = 32)
            int lr = half * 33 + 32;
            int gr = (lr == 65) ? 62 : lr - 1;
            float4 v = *(const float4*)(bc + gr * W + 4 * q);
            *(float4*)(sc + lr * SCOLS + 4 + 4 * q) = v;
            if (lr <= 64) {
                sum += v.x + v.y + v.z + v.w;
                sq  += v.x * v.x + v.y * v.y + v.z * v.z + v.w * v.w;
            }
        }
        // halo columns
        for (int idx = tid; idx < 8 * SROWS; idx += 512) {
            int c2 = idx / SROWS, lr = idx % SROWS;
            int gr = (lr == 0) ? 1 : (lr == 65 ? 62 : lr - 1);
            const float* b2 = content + (size_t)(cbase + c2) * HW + gr * W;
            float* row = s + c2 * CHT + lr * SCOLS;
            row[3]  = b2[1];
            row[68] = b2[62];
        }
        #pragma unroll
        for (int off = 16; off; off >>= 1) {
            sum += __shfl_down_sync(0xffffffffu, sum, off);
            sq  += __shfl_down_sync(0xffffffffu, sq,  off);
        }
        if (lane == 0) { red[warp] = sum; red[16 + warp] = sq; }
    }

    // ---- style -> transposed smem + sd ----
    {
        st[ 0 * 512 + tid] = a0.x;  st[ 1 * 512 + tid] = a0.y;
        st[ 2 * 512 + tid] = a0.z;  st[ 3 * 512 + tid] = a0.w;
        st[ 4 * 512 + tid] = a1.x;  st[ 5 * 512 + tid] = a1.y;
        st[ 6 * 512 + tid] = a1.z;  st[ 7 * 512 + tid] = a1.w;
        st[ 8 * 512 + tid] = a2.x;  st[ 9 * 512 + tid] = a2.y;
        st[10 * 512 + tid] = a2.z;  st[11 * 512 + tid] = a2.w;
        st[12 * 512 + tid] = a3.x;  st[13 * 512 + tid] = a3.y;
        st[14 * 512 + tid] = a3.z;  st[15 * 512 + tid] = a3.w;
        float tot = a0.x + a0.y + a0.z + a0.w + a1.x + a1.y + a1.z + a1.w
                  + a2.x + a2.y + a2.z + a2.w + a3.x + a3.y + a3.z + a3.w;
        sd[tid] = tot * (1.f / 16.f);
    }
    __syncthreads();

    // ============ 2. prep ==================================================
    // d-dot: thread = (j = tid>>6, chunk = tid&63); channels c = chunk + 64*i
    {
        int j  = tid >> 6;
        int cc = tid & 63;
        const float4* w4base = (const float4*)dw_w;
        float acc[9];
        #pragma unroll
        for (int i = 0; i < 9; i++) acc[i] = 0.f;

        #pragma unroll
        for (int i = 0; i < 8; i++) {
            int ch = cc + 64 * i;
            float4 w = w4base[j * 512 + ch];
            float stv[16];
            #pragma unroll
            for (int p = 0; p < 16; p++) stv[p] = st[p * 512 + ch];
            #pragma unroll
            for (int ky = 0; ky < 3; ky++)
                #pragma unroll
                for (int kx = 0; kx < 3; kx++)
                    acc[ky * 3 + kx] += w.x * stv[ky * 4 + kx]
                                      + w.y * stv[ky * 4 + kx + 1]
                                      + w.z * stv[ky * 4 + kx + 4]
                                      + w.w * stv[ky * 4 + kx + 5];
        }
        #pragma unroll
        for (int i = 0; i < 9; i++) {
            #pragma unroll
            for (int off = 16; off; off >>= 1)
                acc[i] += __shfl_xor_sync(0xffffffffu, acc[i], off);
        }
        if (lane == 0) {
            #pragma unroll
            for (int i = 0; i < 9; i++) dredW[warp * 9 + i] = acc[i];
        }
    }
    // bias (warps 0-7) and S (warp 8)
    if (warp < 8) {
        const float* row = pb_w + (size_t)(g * 8 + warp) * 512;
        float acc = 0.f;
        #pragma unroll
        for (int k = 0; k < 16; k++) {
            int c2 = lane + 32 * k;
            acc += row[c2] * sd[c2];
        }
        #pragma unroll
        for (int off = 16; off; off >>= 1)
            acc += __shfl_down_sync(0xffffffffu, acc, off);
        if (lane == 0) fb[warp] = acc + pb_b[g * 8 + warp];
    } else if (warp == 8) {
        const float4* pkw4 = (const float4*)pk_w;
        const float4* sd4  = (const float4*)sd;
        float4 sv0 = sd4[lane], sv1 = sd4[lane + 32];
        float4 sv2 = sd4[lane + 64], sv3 = sd4[lane + 96];
        float acc = 0.f;
        #pragma unroll
        for (int j = 0; j < 8; j++) {
            float4 w0 = pkw4[j * 128 + lane];
            float4 w1 = pkw4[j * 128 + lane + 32];
            float4 w2 = pkw4[j * 128 + lane + 64];
            float4 w3 = pkw4[j * 128 + lane + 96];
            acc += w0.x * sv0.x + w0.y * sv0.y + w0.z * sv0.z + w0.w * sv0.w
                 + w1.x * sv1.x + w1.y * sv1.y + w1.z * sv1.z + w1.w * sv1.w
                 + w2.x * sv2.x + w2.y * sv2.y + w2.z * sv2.z + w2.w * sv2.w
                 + w3.x * sv3.x + w3.y * sv3.y + w3.z * sv3.z + w3.w * sv3.w;
        }
        #pragma unroll
        for (int off = 16; off; off >>= 1)
            acc += __shfl_down_sync(0xffffffffu, acc, off);
        if (lane == 0) {
            float bsum = 0.f;
            #pragma unroll
            for (int j = 0; j < 8; j++) bsum += pk_b[j];
            fS_sh = acc + bsum;
        }
    }
    __syncthreads();

    // ============ 3. finalize ==============================================
    if (tid < 72) {
        int j = tid / 9, pos = tid % 9;
        float v = dredW[(2 * j) * 9 + pos] + dredW[(2 * j + 1) * 9 + pos]
                + dw_b[j];
        fd[tid] = v >= 0.f ? v : 0.01f * v;          // leaky
    }
    if (tid >= 96 && tid < 104) {
        int o = tid - 96;
        float S = red[2 * o] + red[2 * o + 1];
        float Q = red[16 + 2 * o] + red[16 + 2 * o + 1];
        float mean = S * (1.f / HW);
        float var  = (Q - S * S * (1.f / HW)) * (1.f / (HW - 1));  // ddof=1
        fm[o] = mean;
        fr[o] = rsqrtf(var + 1e-5f);
    }
    __syncthreads();

    // ============ conv: 2 rows x 4 cols per thread =========================
    // Neighbor columns via warp shuffle; q==0 / q==15 edges fall back to LDS.
    int r2 = tid >> 4;                    // 0..31
    int q  = tid & 15;
    int q4 = q * 4;                       // output col base
    int h0 = 2 * r2;                      // output rows h0, h0+1
    bool qlo = (q == 0), qhi = (q == 15);

    float D0[4] = {0.f, 0.f, 0.f, 0.f};
    float D1[4] = {0.f, 0.f, 0.f, 0.f};

    #pragma unroll
    for (int j = 0; j < 8; j++) {
        const float* sj = s + j * CHT;
        const float* fj = fd + j * 9;
        #pragma unroll
        for (int rr = 0; rr < 4; rr++) {
            const float* rp = sj + (h0 + rr) * SCOLS + q4;
            float4 f4 = *(const float4*)(rp + 4);   // aligned LDS.128
            float vL = __shfl_up_sync(0xffffffffu, f4.w, 1);
            float vR = __shfl_down_sync(0xffffffffu, f4.x, 1);
            if (qlo) vL = rp[3];
            if (qhi) vR = rp[8];
            if (rr < 3) {
                float a = fj[rr * 3], b2 = fj[rr * 3 + 1], cc2 = fj[rr * 3 + 2];
                D0[0] += a * vL   + b2 * f4.x + cc2 * f4.y;
                D0[1] += a * f4.x + b2 * f4.y + cc2 * f4.z;
                D0[2] += a * f4.y + b2 * f4.z + cc2 * f4.w;
                D0[3] += a * f4.z + b2 * f4.w + cc2 * vR;
            }
            if (rr >= 1) {
                int kr = rr - 1;
                float a = fj[kr * 3], b2 = fj[kr * 3 + 1], cc2 = fj[kr * 3 + 2];
                D1[0] += a * vL   + b2 * f4.x + cc2 * f4.y;
                D1[1] += a * f4.x + b2 * f4.y + cc2 * f4.z;
                D1[2] += a * f4.y + b2 * f4.z + cc2 * f4.w;
                D1[3] += a * f4.z + b2 * f4.w + cc2 * vR;
            }
        }
    }

    float S = fS_sh;
    float* obase = out + (size_t)cbase * HW + h0 * W + q4;

    #pragma unroll
    for (int o = 0; o < 8; o++) {
        const float* so = s + o * CHT;
        float mo = fm[o], ro = fr[o], bo = fb[o];
        float4 r0v, r1v;
        {
            float4 cen = *(const float4*)(so + (h0 + 1) * SCOLS + 4 + q4);
            float p0 = D0[0] * S + bo, p1 = D0[1] * S + bo;
            float p2 = D0[2] * S + bo, p3 = D0[3] * S + bo;
            p0 = p0 >= 0.f ? p0 : 0.01f * p0;
            p1 = p1 >= 0.f ? p1 : 0.01f * p1;
            p2 = p2 >= 0.f ? p2 : 0.01f * p2;
            p3 = p3 >= 0.f ? p3 : 0.01f * p3;
            r0v.x = (cen.x - mo) * ro * p0;
            r0v.y = (cen.y - mo) * ro * p1;
            r0v.z = (cen.z - mo) * ro * p2;
            r0v.w = (cen.w - mo) * ro * p3;
        }
        {
            float4 cen = *(const float4*)(so + (h0 + 2) * SCOLS + 4 + q4);
            float p0 = D1[0] * S + bo, p1 = D1[1] * S + bo;
            float p2 = D1[2] * S + bo, p3 = D1[3] * S + bo;
            p0 = p0 >= 0.f ? p0 : 0.01f * p0;
            p1 = p1 >= 0.f ? p1 : 0.01f * p1;
            p2 = p2 >= 0.f ? p2 : 0.01f * p2;
            p3 = p3 >= 0.f ? p3 : 0.01f * p3;
            r1v.x = (cen.x - mo) * ro * p0;
            r1v.y = (cen.y - mo) * ro * p1;
            r1v.z = (cen.z - mo) * ro * p2;
            r1v.w = (cen.w - mo) * ro * p3;
        }
        __stcs((float4*)(obase + (size_t)o * HW),     r0v);
        __stcs((float4*)(obase + (size_t)o * HW + W), r1v);
    }
}

// ===========================================================================
extern "C" void kernel_launch(void* const* d_in, const int* in_sizes, int n_in,
                              void* d_out, int out_size)
{
    const float* style   = (const float*)d_in[0];
    const float* content = (const float*)d_in[1];
    const float* dw_w    = (const float*)d_in[2];
    const float* dw_b    = (const float*)d_in[3];
    const float* pk_w    = (const float*)d_in[4];
    const float* pk_b    = (const float*)d_in[5];
    const float* pb_w    = (const float*)d_in[6];
    const float* pb_b    = (const float*)d_in[7];
    float* out = (float*)d_out;

    static bool attr_set = false;
    if (!attr_set) {
        cudaFuncSetAttribute(fused_kernel,
                             cudaFuncAttributeMaxDynamicSharedMemorySize,
                             STILE * sizeof(float));
        attr_set = true;
    }

    fused_kernel<<<dim3(NG, N_SAMP), 512, STILE * sizeof(float)>>>(
        content, style, dw_w, dw_b, pk_w, pk_b, pb_w, pb_b, out);
}